// round 3
// baseline (speedup 1.0000x reference)
#include <cuda_runtime.h>
#include <math.h>

// Lane-parallel over the 4-dim system: lane l (mod 4) owns row l of K/G/adj
// and scalar component l of vectors. width=4 shuffles communicate; groups of
// 4 lanes are independent replicas (lanes 4..31 mirror group 0). Lane 0 stores.

#define SHFL(v, j)   __shfl_sync(0xffffffffu, (v), (j), 4)
#define BFLY(v, m)   __shfl_xor_sync(0xffffffffu, (v), (m), 4)

__device__ __forceinline__ float fast_tanh(float s) {
    float e = __expf(2.0f * s);
    return 1.0f - __fdividef(2.0f, e + 1.0f);
}

// butterfly sum within 4-lane group -> result replicated on all 4 lanes
__device__ __forceinline__ float gsum(float v) {
    v += BFLY(v, 1);
    v += BFLY(v, 2);
    return v;
}

__global__ void __launch_bounds__(32, 1)
kuramoto_kernel(const float* __restrict__ x,
                const float* __restrict__ Kp,
                const float* __restrict__ bp,
                const float* __restrict__ Gp,
                const float* __restrict__ adjp,
                float* __restrict__ out)
{
    const int lane = threadIdx.x & 3;
    const bool p1 = (lane & 1) != 0;
    const bool p2 = (lane & 2) != 0;

    // ---- loads: broadcast vectors + per-lane rows (all coalesced/broadcast) ----
    float4 xa = ((const float4*)x)[0];            // angles a[0..3]
    float4 xv = ((const float4*)x)[1];            // velocities v[0..3]
    float4 xx = ((const float4*)x)[2];            // xi[0..3]
    float4 kr4 = ((const float4*)Kp)[lane];       // row `lane` of K
    float4 gr4 = ((const float4*)Gp)[lane];       // row `lane` of G
    float4 ar4 = ((const float4*)adjp)[lane];     // row `lane` of adj
    float  b_own = bp[lane];
    float  a_own = x[lane];
    float  v_own = x[4 + lane];

    float a[4]  = {xa.x, xa.y, xa.z, xa.w};
    float v[4]  = {xv.x, xv.y, xv.z, xv.w};
    float xi[4] = {xx.x, xx.y, xx.z, xx.w};
    float kr[4] = {kr4.x, kr4.y, kr4.z, kr4.w};
    float gr[4] = {gr4.x, gr4.y, gr4.z, gr4.w};
    float ar[4] = {ar4.x, ar4.y, ar4.z, ar4.w};

    // ---- t_own = tanh(K[lane,:].xi + b[lane])  (one warp-wide tanh) ----
    float s = b_own;
    #pragma unroll
    for (int j = 0; j < 4; j++) s = fmaf(kr[j], xi[j], s);
    float t_own = fast_tanh(s);

    // ---- dH = K^T t : lane j contributes kr[i]*t_j ; reduce over lanes ----
    float dH[4];
    #pragma unroll
    for (int i = 0; i < 4; i++) dH[i] = gsum(kr[i] * t_own);   // replicated

    // dH_own = dH[lane] via selects
    float d01 = p1 ? dH[1] : dH[0];
    float d23 = p1 ? dH[3] : dH[2];
    float dH_own = p2 ? d23 : d01;

    // ---- interactions[j] = sum_i adj[i][j]*cos(a_j - a_i)*(v_j - v_i) ----
    // lane i computes its 4 contributions, reduce over lanes.
    float inter[4];
    #pragma unroll
    for (int j = 0; j < 4; j++) {
        float c = __cosf(a[j] - a_own);
        inter[j] = gsum(ar[j] * c * (v[j] - v_own));           // replicated
    }

    // ---- AG row (reused), u = (adj*G)^T dH, dxdt = -1.25*u*inter ----
    float AG[4];
    #pragma unroll
    for (int j = 0; j < 4; j++) AG[j] = ar[j] * gr[j];

    float dxdt[4];
    #pragma unroll
    for (int i = 0; i < 4; i++) {
        float u_i = gsum(AG[i] * dH_own);                      // sum_j A[j][i]G[j][i]dH_j
        dxdt[i] = -1.25f * u_i * inter[i];                     // replicated
    }

    // ---- gamma = 0.1 * lambda_max(G G^T) ----
    // M row (lane i holds row i): M[i][j] = sum_k G[i][k]*G[j][k]
    float mr[4], pr[4];
    #pragma unroll
    for (int j = 0; j < 4; j++) {
        float m = 0.f;
        #pragma unroll
        for (int k = 0; k < 4; k++) m = fmaf(gr[k], SHFL(gr[k], j), m);
        mr[j] = m;
        pr[j] = m;
    }
    // 3 squarings: P <- P*P  (P stays symmetric; M^8 total)
    #pragma unroll
    for (int sq = 0; sq < 3; sq++) {
        float qn[4];
        #pragma unroll
        for (int j = 0; j < 4; j++) {
            float q = 0.f;
            #pragma unroll
            for (int k = 0; k < 4; k++) q = fmaf(pr[k], SHFL(pr[j], k), q);
            qn[j] = q;
        }
        #pragma unroll
        for (int j = 0; j < 4; j++) pr[j] = qn[j];
    }
    // w = M^8 @ ones (per-lane scalar), Rayleigh quotient vs M
    float w_own = pr[0] + pr[1] + pr[2] + pr[3];
    float Mw = 0.f;
    #pragma unroll
    for (int j = 0; j < 4; j++) Mw = fmaf(mr[j], SHFL(w_own, j), Mw);
    float num = gsum(w_own * Mw);
    float den = gsum(w_own * w_own);
    float gamma = 0.1f * __fdividef(num, den);

    // ---- dxi = (J - gamma I) dH + (adj*G) x2 ----
    float JdH[4];
    JdH[0] = fmaf(-gamma, dH[0], -dH[1]);
    JdH[1] = fmaf(-gamma, dH[1],  dH[0]);
    JdH[2] = fmaf(-gamma, dH[2], -dH[3]);
    JdH[3] = fmaf(-gamma, dH[3],  dH[2]);

    float rAG = 0.f;                                           // row dot (per lane)
    #pragma unroll
    for (int j = 0; j < 4; j++) rAG = fmaf(AG[j], v[j], rAG);

    float dxi[4];
    #pragma unroll
    for (int i = 0; i < 4; i++) dxi[i] = JdH[i] + SHFL(rAG, i);

    // ---- store (lane 0 of the warp) ----
    if (threadIdx.x == 0) {
        float4* o4 = (float4*)out;
        o4[0] = make_float4(v[0], v[1], v[2], v[3]);
        o4[1] = make_float4(dxdt[0], dxdt[1], dxdt[2], dxdt[3]);
        o4[2] = make_float4(dxi[0], dxi[1], dxi[2], dxi[3]);
    }
}

extern "C" void kernel_launch(void* const* d_in, const int* in_sizes, int n_in,
                              void* d_out, int out_size)
{
    // metadata order: t(1), x(12), K(16), b(4), G(16), adj(16)
    const float* x   = (const float*)d_in[1];
    const float* K   = (const float*)d_in[2];
    const float* b   = (const float*)d_in[3];
    const float* G   = (const float*)d_in[4];
    const float* adj = (const float*)d_in[5];
    float* out = (float*)d_out;

    kuramoto_kernel<<<1, 32>>>(x, K, b, G, adj, out);
}

// round 4
// speedup vs baseline: 1.4931x; 1.4931x over previous
#include <cuda_runtime.h>
#include <math.h>

// Single working thread, pure scalar, zero shuffles. Eigenvalue via
// trace-power: lambda_max(M) ~ tr(M^16)^(1/16), M = G G^T symmetric PSD.
// tr(M^16) = ||M^8||_F^2; M^8 from 3 symmetric products (10 dots each).

__device__ __forceinline__ float fast_tanh(float s) {
    float e = __expf(2.0f * s);
    return 1.0f - __fdividef(2.0f, e + 1.0f);
}

// T = S*S for symmetric S (full 16-reg storage, compute 10 unique entries)
__device__ __forceinline__ void sym_square(const float S[16], float T[16]) {
    #pragma unroll
    for (int i = 0; i < 4; i++) {
        #pragma unroll
        for (int j = i; j < 4; j++) {
            float s = 0.f;
            #pragma unroll
            for (int k = 0; k < 4; k++) s = fmaf(S[i*4+k], S[k*4+j], s);
            T[i*4+j] = s;
            T[j*4+i] = s;
        }
    }
}

__global__ void __launch_bounds__(32, 1)
kuramoto_kernel(const float* __restrict__ x,
                const float* __restrict__ Kp,
                const float* __restrict__ bp,
                const float* __restrict__ Gp,
                const float* __restrict__ adjp,
                float* __restrict__ out)
{
    if (threadIdx.x != 0) return;

    // ---- front-batched vector loads (max MLP) ----
    float4 xa = ((const float4*)x)[0];
    float4 xv = ((const float4*)x)[1];
    float4 xx = ((const float4*)x)[2];
    float4 Kr0 = ((const float4*)Kp)[0], Kr1 = ((const float4*)Kp)[1],
           Kr2 = ((const float4*)Kp)[2], Kr3 = ((const float4*)Kp)[3];
    float4 Gr0 = ((const float4*)Gp)[0], Gr1 = ((const float4*)Gp)[1],
           Gr2 = ((const float4*)Gp)[2], Gr3 = ((const float4*)Gp)[3];
    float4 Ar0 = ((const float4*)adjp)[0], Ar1 = ((const float4*)adjp)[1],
           Ar2 = ((const float4*)adjp)[2], Ar3 = ((const float4*)adjp)[3];
    float4 bb  = ((const float4*)bp)[0];

    float a[4]  = {xa.x, xa.y, xa.z, xa.w};
    float v[4]  = {xv.x, xv.y, xv.z, xv.w};
    float xi[4] = {xx.x, xx.y, xx.z, xx.w};
    float K[16] = {Kr0.x,Kr0.y,Kr0.z,Kr0.w, Kr1.x,Kr1.y,Kr1.z,Kr1.w,
                   Kr2.x,Kr2.y,Kr2.z,Kr2.w, Kr3.x,Kr3.y,Kr3.z,Kr3.w};
    float G[16] = {Gr0.x,Gr0.y,Gr0.z,Gr0.w, Gr1.x,Gr1.y,Gr1.z,Gr1.w,
                   Gr2.x,Gr2.y,Gr2.z,Gr2.w, Gr3.x,Gr3.y,Gr3.z,Gr3.w};
    float A[16] = {Ar0.x,Ar0.y,Ar0.z,Ar0.w, Ar1.x,Ar1.y,Ar1.z,Ar1.w,
                   Ar2.x,Ar2.y,Ar2.z,Ar2.w, Ar3.x,Ar3.y,Ar3.z,Ar3.w};
    float bv[4] = {bb.x, bb.y, bb.z, bb.w};

    // ---- gamma = 0.1 * lambda_max(G G^T), trace-power method ----
    float M[16];
    #pragma unroll
    for (int i = 0; i < 4; i++) {
        #pragma unroll
        for (int j = i; j < 4; j++) {
            float s = 0.f;
            #pragma unroll
            for (int k = 0; k < 4; k++) s = fmaf(G[i*4+k], G[j*4+k], s);
            M[i*4+j] = s; M[j*4+i] = s;
        }
    }
    float M2[16], M4[16], M8[16];
    sym_square(M,  M2);
    sym_square(M2, M4);
    sym_square(M4, M8);
    float tr16 = 0.f;
    #pragma unroll
    for (int i = 0; i < 16; i++) tr16 = fmaf(M8[i], M8[i], tr16);
    // lambda ~ tr(M^16)^(1/16)
    float gamma = 0.1f * exp2f(__log2f(tr16) * 0.0625f);

    // ---- dH = K^T tanh(K xi + b) ----
    float t1[4];
    #pragma unroll
    for (int i = 0; i < 4; i++) {
        float s = bv[i];
        #pragma unroll
        for (int j = 0; j < 4; j++) s = fmaf(K[i*4+j], xi[j], s);
        t1[i] = fast_tanh(s);
    }
    float dH[4];
    #pragma unroll
    for (int i = 0; i < 4; i++) {
        float s = 0.f;
        #pragma unroll
        for (int j = 0; j < 4; j++) s = fmaf(K[j*4+i], t1[j], s);
        dH[i] = s;
    }

    // ---- interactions (cos symmetric: 6 unique MUFU) ----
    float c[4][4];
    c[0][0] = c[1][1] = c[2][2] = c[3][3] = 1.0f;
    c[0][1] = c[1][0] = __cosf(a[0] - a[1]);
    c[0][2] = c[2][0] = __cosf(a[0] - a[2]);
    c[0][3] = c[3][0] = __cosf(a[0] - a[3]);
    c[1][2] = c[2][1] = __cosf(a[1] - a[2]);
    c[1][3] = c[3][1] = __cosf(a[1] - a[3]);
    c[2][3] = c[3][2] = __cosf(a[2] - a[3]);

    float inter[4];
    #pragma unroll
    for (int j = 0; j < 4; j++) {
        float s = 0.f;
        #pragma unroll
        for (int i = 0; i < 4; i++)
            s = fmaf(A[i*4+j] * c[i][j], v[j] - v[i], s);
        inter[j] = s;
    }

    // ---- AG = adj .* G (reused), dxdt, dxi ----
    float AG[16];
    #pragma unroll
    for (int i = 0; i < 16; i++) AG[i] = A[i] * G[i];

    float dxdt[4];
    #pragma unroll
    for (int i = 0; i < 4; i++) {
        float s = 0.f;
        #pragma unroll
        for (int j = 0; j < 4; j++) s = fmaf(AG[j*4+i], dH[j], s);
        dxdt[i] = -1.25f * s * inter[i];
    }

    float JdH[4];
    JdH[0] = fmaf(-gamma, dH[0], -dH[1]);
    JdH[1] = fmaf(-gamma, dH[1],  dH[0]);
    JdH[2] = fmaf(-gamma, dH[2], -dH[3]);
    JdH[3] = fmaf(-gamma, dH[3],  dH[2]);

    float dxi[4];
    #pragma unroll
    for (int i = 0; i < 4; i++) {
        float s = 0.f;
        #pragma unroll
        for (int j = 0; j < 4; j++) s = fmaf(AG[i*4+j], v[j], s);
        dxi[i] = JdH[i] + s;
    }

    // ---- stores ----
    float4* o4 = (float4*)out;
    o4[0] = make_float4(v[0], v[1], v[2], v[3]);
    o4[1] = make_float4(dxdt[0], dxdt[1], dxdt[2], dxdt[3]);
    o4[2] = make_float4(dxi[0], dxi[1], dxi[2], dxi[3]);
}

extern "C" void kernel_launch(void* const* d_in, const int* in_sizes, int n_in,
                              void* d_out, int out_size)
{
    // metadata order: t(1), x(12), K(16), b(4), G(16), adj(16)
    const float* x   = (const float*)d_in[1];
    const float* K   = (const float*)d_in[2];
    const float* b   = (const float*)d_in[3];
    const float* G   = (const float*)d_in[4];
    const float* adj = (const float*)d_in[5];
    float* out = (float*)d_out;

    kuramoto_kernel<<<1, 32>>>(x, K, b, G, adj, out);
}